// round 10
// baseline (speedup 1.0000x reference)
#include <cuda_runtime.h>
#include <cuda_bf16.h>

// result(row) = sum over 28 chunk-pair tables T_(A,B)[nib_A][nib_B],
// 32 bits -> 8 nibbles. All 528 order<=2 terms folded into the tables.
// Eval: 2 threads per row. Warp = 16 rows, 4 batched lane-transposed
// LDG.128, butterfly nibble pack, 14 smem lookups per thread, shfl combine.

#define NPAIRS 28
#define TABSZ (NPAIRS * 256)   // 7168 floats = 28 KB

__device__ float g_tab[TABSZ];

// variables index for pair (i,j), i<j (itertools.combinations order)
__device__ __forceinline__ int pair_v(int i, int j) {
    return 32 + i * 31 - (i * (i - 1)) / 2 + (j - i - 1);
}

__global__ void KOBE_76948634075865_precompute(const float* __restrict__ vars) {
    int p = blockIdx.x;          // chunk-pair index 0..27
    int t = threadIdx.x;         // entry index 0..255
    int a = t >> 4;              // nibble value of chunk A
    int b = t & 15;              // nibble value of chunk B

    // decode p -> (A,B), A<B over 8 chunks
    int A = 0, rem = p, cnt = 7;
    while (rem >= cnt) { rem -= cnt; cnt--; A++; }
    int B = A + 1 + rem;

    float sa[4], sb[4];
#pragma unroll
    for (int k = 0; k < 4; k++) {
        sa[k] = 1.0f - 2.0f * (float)((a >> k) & 1);
        sb[k] = 1.0f - 2.0f * (float)((b >> k) & 1);
    }

    float acc = 0.0f;

#pragma unroll
    for (int i2 = 0; i2 < 4; i2++) {
        int i = 4 * A + i2;
#pragma unroll
        for (int j2 = 0; j2 < 4; j2++) {
            int j = 4 * B + j2;
            acc += vars[pair_v(i, j)] * sa[i2] * sb[j2];
        }
    }

    if (B == 7) {
#pragma unroll
        for (int i2 = 0; i2 < 4; i2++) {
            int i = 4 * A + i2;
            acc += vars[i] * sa[i2];
#pragma unroll
            for (int j2 = i2 + 1; j2 < 4; j2++) {
                int j = 4 * A + j2;
                acc += vars[pair_v(i, j)] * sa[i2] * sa[j2];
            }
        }
        if (A == 6) {
#pragma unroll
            for (int i2 = 0; i2 < 4; i2++) {
                int i = 28 + i2;
                acc += vars[i] * sb[i2];
#pragma unroll
                for (int j2 = i2 + 1; j2 < 4; j2++) {
                    int j = 28 + j2;
                    acc += vars[pair_v(i, j)] * sb[i2] * sb[j2];
                }
            }
        }
    }

    g_tab[p * 256 + a * 16 + b] = acc;
}

// lookup helper: table p, nibble pair (na, nb)
#define LOOK(p, na, nb) tab[(p) * 256 + (na) * 16 + (nb)]

__global__ __launch_bounds__(256, 6) void KOBE_76948634075865_eval(
    const int4* __restrict__ bits, float* __restrict__ out, int batch) {
    __shared__ float tab[TABSZ];
    int tid = threadIdx.x;
    int warp = tid >> 5, lane = tid & 31;
    int grp = lane >> 3;           // 8-lane group (0..3)
    int c = lane & 7;              // chunk slot 0..7
    int half = c >> 2;             // 0 or 1: which 14 lookups this lane does
    int rsel = c & 3;              // which load iteration's row this lane owns

    int base = blockIdx.x * 128 + warp * 16;    // first row of this warp
    const int4* p = bits + (size_t)base * 8;
    bool full = (base + 16 <= batch);

    // 4 batched lane-transposed LDG.128: iteration i covers rows base+4i..+3.
    int4 xs[4];
#pragma unroll
    for (int i = 0; i < 4; i++) {
        int lin = i * 32 + lane;
        if (full || base + (lin >> 3) < batch) xs[i] = p[lin];
        else xs[i] = make_int4(0, 0, 0, 0);
    }

    // Cooperative table fill (28 KB = 1792 float4, 7 per thread)
    {
        const float4* src = (const float4*)g_tab;
        float4* dst = (float4*)tab;
#pragma unroll
        for (int k = 0; k < 7; k++) dst[tid + k * 256] = src[tid + k * 256];
    }

    // Butterfly-OR pack within each 8-lane group; lane keeps row base+4*rsel+grp
    unsigned packed = 0;
#pragma unroll
    for (int i = 0; i < 4; i++) {
        int nib = xs[i].x + 2 * xs[i].y + 4 * xs[i].z + 8 * xs[i].w;
        unsigned v = (unsigned)nib << (4 * c);
        v |= __shfl_xor_sync(0xffffffffu, v, 1);
        v |= __shfl_xor_sync(0xffffffffu, v, 2);
        v |= __shfl_xor_sync(0xffffffffu, v, 4);
        if (i == rsel) packed = v;
    }
    __syncthreads();

    int n0 = packed & 15,          n1 = (packed >> 4) & 15;
    int n2 = (packed >> 8) & 15,   n3 = (packed >> 12) & 15;
    int n4 = (packed >> 16) & 15,  n5 = (packed >> 20) & 15;
    int n6 = (packed >> 24) & 15,  n7 = (packed >> 28) & 15;

    float a0 = 0.f, a1 = 0.f;
    if (half == 0) {   // tables p0..p13: (0,*) and (1,2..7), (2,3)
        a0 += LOOK( 0, n0, n1);  a1 += LOOK( 1, n0, n2);
        a0 += LOOK( 2, n0, n3);  a1 += LOOK( 3, n0, n4);
        a0 += LOOK( 4, n0, n5);  a1 += LOOK( 5, n0, n6);
        a0 += LOOK( 6, n0, n7);  a1 += LOOK( 7, n1, n2);
        a0 += LOOK( 8, n1, n3);  a1 += LOOK( 9, n1, n4);
        a0 += LOOK(10, n1, n5);  a1 += LOOK(11, n1, n6);
        a0 += LOOK(12, n1, n7);  a1 += LOOK(13, n2, n3);
    } else {           // tables p14..p27
        a0 += LOOK(14, n2, n4);  a1 += LOOK(15, n2, n5);
        a0 += LOOK(16, n2, n6);  a1 += LOOK(17, n2, n7);
        a0 += LOOK(18, n3, n4);  a1 += LOOK(19, n3, n5);
        a0 += LOOK(20, n3, n6);  a1 += LOOK(21, n3, n7);
        a0 += LOOK(22, n4, n5);  a1 += LOOK(23, n4, n6);
        a0 += LOOK(24, n4, n7);  a1 += LOOK(25, n5, n6);
        a0 += LOOK(26, n5, n7);  a1 += LOOK(27, n6, n7);
    }
    float partial = a0 + a1;
    // partner lane is c ^ 4 (same row, other half)
    float total = partial + __shfl_xor_sync(0xffffffffu, partial, 4);

    int myrow = base + 4 * rsel + grp;
    if (half == 0 && myrow < batch) out[myrow] = total;
}

extern "C" void kernel_launch(void* const* d_in, const int* in_sizes, int n_in,
                              void* d_out, int out_size) {
    const int4* bits = (const int4*)d_in[0];    // [BATCH, 32] int32
    const float* vars = (const float*)d_in[1];  // [528] float32
    int batch = in_sizes[0] / 32;
    float* out = (float*)d_out;

    KOBE_76948634075865_precompute<<<NPAIRS, 256>>>(vars);

    int blocks = (batch + 127) / 128;           // 128 rows per 256-thr block
    KOBE_76948634075865_eval<<<blocks, 256>>>(bits, out, batch);
}

// round 11
// speedup vs baseline: 1.1599x; 1.1599x over previous
#include <cuda_runtime.h>
#include <cuda_bf16.h>

// Single fused kernel. result(row) = sum over 28 chunk-pair tables
// T_(A,B)[nib_A][nib_B] (32 bits -> 8 nibbles; all 528 order<=2 terms folded
// into the tables, built per-block from `variables`).
// Row data staged global->shared via cp.async with XOR swizzle; per-row read
// is 8 conflict-free LDS.128 (no shuffles).

#define ROWS_PER_TILE 256
#define TILE_BYTES (ROWS_PER_TILE * 128)        // 32768
#define SMEM_VS    0                             // 528 floats = 2112 B
#define SMEM_TAB   2112                          // 7168 floats = 28672 B
#define SMEM_BUF0  30784
#define SMEM_BUF1  (30784 + TILE_BYTES)          // 63552
#define SMEM_TOTAL (SMEM_BUF1 + TILE_BYTES)      // 96320 B

__device__ __forceinline__ unsigned smem_addr_u32(const void* p) {
    unsigned a;
    asm("{ .reg .u64 t; cvta.to.shared.u64 t, %1; cvt.u32.u64 %0, t; }"
        : "=r"(a) : "l"(p));
    return a;
}
__device__ __forceinline__ void cp16(unsigned dst, const void* src) {
    asm volatile("cp.async.cg.shared.global [%0], [%1], 16;"
                 :: "r"(dst), "l"(src));
}
#define CP_COMMIT() asm volatile("cp.async.commit_group;")
#define CP_WAIT(n)  asm volatile("cp.async.wait_group %0;" :: "n"(n))

// variables index for pair (i,j), i<j (itertools.combinations order)
__device__ __forceinline__ int pair_v(int i, int j) {
    return 32 + i * 31 - (i * (i - 1)) / 2 + (j - i - 1);
}

__device__ __forceinline__ float row_energy(const float* tab, const int4* buf,
                                            int tid) {
    int sw = tid & 7;
    const int4* rp = buf + tid * 8;
    int n[8];
#pragma unroll
    for (int c = 0; c < 8; c++) {
        int4 x = rp[c ^ sw];
        n[c] = x.x + 2 * x.y + 4 * x.z + 8 * x.w;
    }
    float a0 = 0.f, a1 = 0.f, a2 = 0.f, a3 = 0.f;
    int idx = 0;
#pragma unroll
    for (int A = 0; A < 8; A++) {
#pragma unroll
        for (int B = A + 1; B < 8; B++) {
            float v = tab[idx * 256 + n[A] * 16 + n[B]];
            if ((idx & 3) == 0)      a0 += v;
            else if ((idx & 3) == 1) a1 += v;
            else if ((idx & 3) == 2) a2 += v;
            else                     a3 += v;
            idx++;
        }
    }
    return (a0 + a1) + (a2 + a3);
}

__global__ __launch_bounds__(256, 2) void KOBE_76948634075865_fused(
    const char* __restrict__ bits, const float* __restrict__ vars,
    float* __restrict__ out, int batch) {
    extern __shared__ float smem[];
    unsigned sbase = smem_addr_u32(smem);
    int tid = threadIdx.x;

    // group 0: variables (2112 B = 132 x 16B)
    if (tid < 132) cp16(sbase + SMEM_VS + tid * 16, (const char*)vars + tid * 16);
    CP_COMMIT();

    // tiles: block handles rows [b*256, b*256+255] and [(b+G)*256, ...]
    int G = gridDim.x;
    long long row0 = (long long)blockIdx.x * ROWS_PER_TILE;
    long long row1 = (long long)(blockIdx.x + G) * ROWS_PER_TILE;

    // group 1: tile0, group 2: tile1 (8 x 16B chunks per thread, contiguous
    // global, XOR-swizzled shared)
#pragma unroll
    for (int k = 0; k < 8; k++) {
        int g = k * 256 + tid;               // chunk index in tile
        int r = g >> 3, c = g & 7;
        if (row0 + r < batch)
            cp16(sbase + SMEM_BUF0 + r * 128 + ((c ^ (r & 7)) << 4),
                 bits + (row0 * 128) + g * 16);
    }
    CP_COMMIT();
#pragma unroll
    for (int k = 0; k < 8; k++) {
        int g = k * 256 + tid;
        int r = g >> 3, c = g & 7;
        if (row1 + r < batch)
            cp16(sbase + SMEM_BUF1 + r * 128 + ((c ^ (r & 7)) << 4),
                 bits + (row1 * 128) + g * 16);
    }
    CP_COMMIT();

    CP_WAIT(2);              // variables landed
    __syncthreads();

    // ---- build all 28 tables; thread = entry (a,b), loops over p ----
    const float* vs = smem;          // 528 floats
    float* tab = smem + 528;         // 7168 floats
    {
        int a = tid >> 4, b = tid & 15;
        float sa[4], sb[4];
#pragma unroll
        for (int k = 0; k < 4; k++) {
            sa[k] = 1.0f - 2.0f * (float)((a >> k) & 1);
            sb[k] = 1.0f - 2.0f * (float)((b >> k) & 1);
        }
        float sg[16];
#pragma unroll
        for (int i2 = 0; i2 < 4; i2++)
#pragma unroll
            for (int j2 = 0; j2 < 4; j2++) sg[i2 * 4 + j2] = sa[i2] * sb[j2];

        int p = 0;
#pragma unroll
        for (int A = 0; A < 8; A++) {
#pragma unroll
            for (int B = A + 1; B < 8; B++) {
                float acc = 0.0f;
#pragma unroll
                for (int i2 = 0; i2 < 4; i2++)
#pragma unroll
                    for (int j2 = 0; j2 < 4; j2++)
                        acc = fmaf(vs[pair_v(4 * A + i2, 4 * B + j2)],
                                   sg[i2 * 4 + j2], acc);
                if (B == 7) {
#pragma unroll
                    for (int i2 = 0; i2 < 4; i2++) {
                        acc = fmaf(vs[4 * A + i2], sa[i2], acc);   // linear A
#pragma unroll
                        for (int j2 = i2 + 1; j2 < 4; j2++)
                            acc = fmaf(vs[pair_v(4 * A + i2, 4 * A + j2)],
                                       sa[i2] * sa[j2], acc);      // intra A
                    }
                    if (A == 6) {
#pragma unroll
                        for (int i2 = 0; i2 < 4; i2++) {
                            acc = fmaf(vs[28 + i2], sb[i2], acc);  // linear 7
#pragma unroll
                            for (int j2 = i2 + 1; j2 < 4; j2++)
                                acc = fmaf(vs[pair_v(28 + i2, 28 + j2)],
                                           sb[i2] * sb[j2], acc);  // intra 7
                        }
                    }
                }
                tab[p * 256 + tid] = acc;
                p++;
            }
        }
    }

    CP_WAIT(1);              // tile0 landed (and publishes tab below)
    __syncthreads();

    {
        const int4* buf0 = (const int4*)((const char*)smem + SMEM_BUF0);
        long long myrow = row0 + tid;
        if (myrow < batch) out[myrow] = row_energy(tab, buf0, tid);
    }

    CP_WAIT(0);              // tile1 landed
    __syncthreads();

    {
        const int4* buf1 = (const int4*)((const char*)smem + SMEM_BUF1);
        long long myrow = row1 + tid;
        if (myrow < batch) out[myrow] = row_energy(tab, buf1, tid);
    }
}

extern "C" void kernel_launch(void* const* d_in, const int* in_sizes, int n_in,
                              void* d_out, int out_size) {
    const char* bits = (const char*)d_in[0];    // [BATCH, 32] int32
    const float* vars = (const float*)d_in[1];  // [528] float32
    int batch = in_sizes[0] / 32;
    float* out = (float*)d_out;

    cudaFuncSetAttribute(KOBE_76948634075865_fused,
                         cudaFuncAttributeMaxDynamicSharedMemorySize,
                         SMEM_TOTAL);

    // each block covers 2 tiles of 256 rows
    int G = (batch + 2 * ROWS_PER_TILE - 1) / (2 * ROWS_PER_TILE);   // 256
    KOBE_76948634075865_fused<<<G, 256, SMEM_TOTAL>>>(bits, vars, out, batch);
}